// round 16
// baseline (speedup 1.0000x reference)
#include <cuda_runtime.h>
#include <cuda_fp16.h>
#include <math.h>
#include <stdint.h>

#define B_ 4096
#define D_ 768
#define E_ 16
#define H_ 768
#define C_ 1000
#define TK_ 4

#define MARKET_OFF 0
#define ALL_OFF    ((size_t)B_ * C_)
#define GATE_OFF   (ALL_OFF + (size_t)E_ * B_ * C_)

// ---------------- device scratch ----------------
__device__ __half g_xn[(size_t)B_ * D_];
__device__ __half g_w1t[(size_t)E_ * H_ * D_];     // [e][h][d], ln_g folded
__device__ __half g_w2t[(size_t)E_ * 1024 * H_];   // [e][c pad1024][h]
__device__ __half g_h[(size_t)E_ * B_ * H_];       // [e][b][h], gelu output
__device__ float g_b1f[E_ * H_];
__device__ int   g_tidx[B_ * TK_];
__device__ float g_tw[B_ * TK_];

// ---------------- PTX helpers (target-portable only) ----------------
__device__ __forceinline__ uint32_t smem_u32(const void* p) {
    uint32_t a;
    asm("{ .reg .u64 t; cvta.to.shared.u64 t, %1; cvt.u32.u64 %0, t; }"
        : "=r"(a) : "l"(p));
    return a;
}
__device__ __forceinline__ void cp16(uint32_t dst, const void* src) {
    asm volatile("cp.async.cg.shared.global [%0], [%1], 16;" :: "r"(dst), "l"(src));
}
#define CP_COMMIT() asm volatile("cp.async.commit_group;" ::: "memory")
#define CP_WAIT(n)  asm volatile("cp.async.wait_group %0;" :: "n"(n) : "memory")

__device__ __forceinline__ void ldmx4(uint32_t* r, uint32_t addr) {
    asm volatile("ldmatrix.sync.aligned.m8n8.x4.shared.b16 {%0,%1,%2,%3}, [%4];"
                 : "=r"(r[0]), "=r"(r[1]), "=r"(r[2]), "=r"(r[3]) : "r"(addr));
}
__device__ __forceinline__ void mma16816(float* d, const uint32_t* a, const uint32_t* b) {
    asm volatile(
        "mma.sync.aligned.m16n8k16.row.col.f32.f16.f16.f32 "
        "{%0,%1,%2,%3}, {%4,%5,%6,%7}, {%8,%9}, {%0,%1,%2,%3};"
        : "+f"(d[0]), "+f"(d[1]), "+f"(d[2]), "+f"(d[3])
        : "r"(a[0]), "r"(a[1]), "r"(a[2]), "r"(a[3]), "r"(b[0]), "r"(b[1]));
}

// ===================================================================
// Merged weight prep: z<16 -> w1 (transpose + ln_g fold + b1f atomics),
// z>=16 -> w2 (transpose + pad). Homogeneous 32x32 transpose tiles.
// ===================================================================
__global__ void prep_w_kernel(const float* __restrict__ w1,
                              const float* __restrict__ ln_g,
                              const float* __restrict__ ln_b,
                              const float* __restrict__ w2) {
    __shared__ float t[32][33];
    int tx = threadIdx.x, ty = threadIdx.y;
    int z = blockIdx.z;

    if (z < E_) {
        if (blockIdx.x >= 24) return;   // w1 uses 24 h-blocks
        __shared__ float ps[8][32];
        int e = z;
        int h0 = blockIdx.x * 32, d0 = blockIdx.y * 32;
        float part = 0.f;
        #pragma unroll
        for (int i = 0; i < 32; i += 8) {
            int d = d0 + ty + i;
            float raw = w1[((size_t)e * D_ + d) * H_ + h0 + tx];
            part += ln_b[e * D_ + d] * raw;
            t[ty + i][tx] = ln_g[e * D_ + d] * raw;
        }
        ps[ty][tx] = part;
        __syncthreads();
        if (ty == 0) {
            float acc = 0.f;
            #pragma unroll
            for (int q = 0; q < 8; q++) acc += ps[q][tx];
            atomicAdd(&g_b1f[e * H_ + h0 + tx], acc);
        }
        #pragma unroll
        for (int i = 0; i < 32; i += 8) {
            int h = h0 + ty + i;
            g_w1t[((size_t)e * H_ + h) * D_ + d0 + tx] =
                __float2half_rn(t[tx][ty + i]);
        }
    } else {
        int e = z - E_;
        int c0 = blockIdx.x * 32, h0 = blockIdx.y * 32;
        #pragma unroll
        for (int i = 0; i < 32; i += 8) {
            int h = h0 + ty + i;
            int c = c0 + tx;
            t[ty + i][tx] = (c < C_) ? w2[((size_t)e * H_ + h) * C_ + c] : 0.f;
        }
        __syncthreads();
        #pragma unroll
        for (int i = 0; i < 32; i += 8) {
            int c = c0 + ty + i;
            g_w2t[((size_t)e * 1024 + c) * H_ + h0 + tx] =
                __float2half_rn(t[tx][ty + i]);
        }
    }
}

// ===================================================================
// Router + LayerNorm (writes xn as fp16). First 48 blocks also seed
// g_b1f = b1 (router runs before prep_w, so ordering is safe).
// ===================================================================
__global__ __launch_bounds__(256) void router_ln_kernel(
    const float* __restrict__ F, const float* __restrict__ RW,
    const float* __restrict__ RB, const float* __restrict__ b1,
    float* __restrict__ gate_out) {
    int b = blockIdx.x;
    int tid = threadIdx.x;

    if (b < 48) {
        int i = b * 256 + tid;
        if (i < E_ * H_) g_b1f[i] = b1[i];
    }

    __shared__ float xs[D_];
    __shared__ float red[256];
    __shared__ float red2[256];
    __shared__ float gl[16][17];
    __shared__ float smean, srstd;

    const float* f = F + (size_t)b * D_;
    float s = 0.f, s2 = 0.f;
    for (int i = tid; i < D_; i += 256) {
        float v = f[i];
        xs[i] = v; s += v; s2 += v * v;
    }
    red[tid] = s; red2[tid] = s2;
    __syncthreads();
    for (int o = 128; o > 0; o >>= 1) {
        if (tid < o) { red[tid] += red[tid + o]; red2[tid] += red2[tid + o]; }
        __syncthreads();
    }
    if (tid == 0) {
        float mean = red[0] * (1.f / D_);
        float var = red2[0] * (1.f / D_) - mean * mean;
        smean = mean;
        srstd = rsqrtf(var + 1e-5f);
    }
    __syncthreads();
    float mean = smean, rstd = srstd;
    for (int i = tid; i < D_; i += 256)
        g_xn[(size_t)b * D_ + i] = __float2half_rn((xs[i] - mean) * rstd);

    int e = tid & 15, p = tid >> 4;
    float acc = 0.f;
    for (int d = p; d < D_; d += 16) acc += xs[d] * RW[d * E_ + e];
    gl[p][e] = acc;
    __syncthreads();
    if (tid < 16) {
        float l = RB[tid];
        #pragma unroll
        for (int q = 0; q < 16; q++) l += gl[q][tid];
        red[tid] = l;
    }
    __syncthreads();
    if (tid == 0) {
        float lg[16];
        float mx = -3.4e38f;
        #pragma unroll
        for (int i = 0; i < 16; i++) { lg[i] = red[i]; mx = fmaxf(mx, lg[i]); }
        float sum = 0.f;
        #pragma unroll
        for (int i = 0; i < 16; i++) { lg[i] = expf(lg[i] - mx); sum += lg[i]; }
        float inv = 1.f / sum;
        #pragma unroll
        for (int i = 0; i < 16; i++) {
            lg[i] *= inv;
            gate_out[(size_t)b * 16 + i] = lg[i];
        }
        float tmp[16];
        #pragma unroll
        for (int i = 0; i < 16; i++) tmp[i] = lg[i];
        int idx[TK_]; float val[TK_]; float vs = 0.f;
        for (int k = 0; k < TK_; k++) {
            int bj = 0; float bv = tmp[0];
            #pragma unroll
            for (int j = 1; j < 16; j++)
                if (tmp[j] > bv) { bv = tmp[j]; bj = j; }
            idx[k] = bj; val[k] = bv; vs += bv;
            tmp[bj] = -1.f;
        }
        float ivs = 1.f / vs;
        for (int k = 0; k < TK_; k++) {
            g_tidx[b * TK_ + k] = idx[k];
            g_tw[b * TK_ + k] = val[k] * ivs;
        }
    }
}

// ===================================================================
// mma.sync GEMM: CTA 128x128x96, 8 warps (2m x 4n), warp tile 64x32.
// BK=96 (ROWB=208 conflict-free: row stride 13 quad-banks, coprime 32),
// STAGES=2, 2 CTAs/SM. 8 chunks -> 33% fewer barriers than BK=64.
// Next-chunk cp.async issued in the ks=0 MMA shadow (R14's win).
// single-pass fp16, fp32 accum. K=768.
// EPI=1: A=xn, B=w1t; epilogue bias+gelu -> g_h (fp16)
// EPI=2: A=g_h, B=w2t; epilogue bias -> allp fp32 (bounds C=1000)
// ===================================================================
#define BK 96
#define STAGES 2
#define ROWB 208u                 // 96 fp16 (192B) + 16B pad
#define OFF_A 0u
#define OFF_B 26624u              // 128*208
#define STG   53248u              // 256*208
#define GEMM_SMEM (STAGES * 53248)  // 106496
#define NCH (D_ / BK)             // 8
#define NKS (BK / 16)             // 6

template <int EPI>
__global__ __launch_bounds__(256, 2) void gemm_mma_kernel(
    const float* __restrict__ b2, float* __restrict__ allp) {
    const int e  = blockIdx.z;
    const int m0 = blockIdx.y * 128;
    const int n0 = blockIdx.x * 128;
    const int tid  = threadIdx.x;
    const int lane = tid & 31;
    const int wid  = tid >> 5;
    const int wm   = wid >> 2;   // 0..1
    const int wn   = wid & 3;    // 0..3

    extern __shared__ char smem[];
    uint32_t sb = smem_u32(smem);

    const char *gA, *gB;
    if (EPI == 1) {
        gA = (const char*)(g_xn + (size_t)m0 * D_);
        gB = (const char*)(g_w1t + ((size_t)e * H_ + n0) * D_);
    } else {
        gA = (const char*)(g_h + ((size_t)e * B_ + m0) * H_);
        gB = (const char*)(g_w2t + ((size_t)e * 1024 + n0) * H_);
    }

    // per chunk: 128 rows x 192 B = 12 segs of 16B per row, A and B each.
    auto load_chunk = [&](int stage, int kc) {
        uint32_t base = sb + (uint32_t)stage * STG;
        size_t kb = (size_t)kc * 192;            // 96 fp16 = 192 B along K
        #pragma unroll
        for (int it = 0; it < 6; it++) {          // A: 128*12 = 1536 ops /256
            int id = tid + it * 256;
            int r = id / 12, ch = id % 12;
            uint32_t so = (uint32_t)r * ROWB + ch * 16;
            size_t go = (size_t)r * 1536 + kb + ch * 16;
            cp16(base + OFF_A + so, gA + go);
        }
        #pragma unroll
        for (int it = 0; it < 6; it++) {          // B: same shape
            int id = tid + it * 256;
            int r = id / 12, ch = id % 12;
            uint32_t so = (uint32_t)r * ROWB + ch * 16;
            size_t go = (size_t)r * 1536 + kb + ch * 16;
            cp16(base + OFF_B + so, gB + go);
        }
    };

    float acc[4][4][4];
    #pragma unroll
    for (int i = 0; i < 4; i++)
        #pragma unroll
        for (int j = 0; j < 4; j++)
            #pragma unroll
            for (int q = 0; q < 4; q++) acc[i][j][q] = 0.f;

    const uint32_t a_off = (uint32_t)(lane & 15) * ROWB + (uint32_t)(lane >> 4) * 16;
    const uint32_t b_off = ((uint32_t)((lane & 7) + ((lane >> 4) << 3))) * ROWB +
                           (uint32_t)((lane >> 3) & 1) * 16;
    const uint32_t aw = (uint32_t)(wm * 64) * ROWB;
    const uint32_t bw = (uint32_t)(wn * 32) * ROWB;

    // prologue: fill 1 buffer
    load_chunk(0, 0);
    CP_COMMIT();

    int st = 0;
    for (int c = 0; c < NCH; c++) {
        CP_WAIT(0);
        __syncthreads();

        uint32_t base = sb + (uint32_t)st * STG;

        // ---- ks = 0: straight to ldsm+MMA after the barrier ----
        {
            uint32_t bh[8];
            #pragma unroll
            for (int q = 0; q < 2; q++)
                ldmx4(&bh[q * 4], base + OFF_B + bw + (uint32_t)(q * 16) * ROWB + b_off);
            #pragma unroll
            for (int mf = 0; mf < 4; mf++) {
                uint32_t ah[4];
                ldmx4(ah, base + OFF_A + aw + (uint32_t)(mf * 16) * ROWB + a_off);
                #pragma unroll
                for (int nf = 0; nf < 4; nf++)
                    mma16816(acc[mf][nf], ah, &bh[nf * 2]);
            }
        }

        // ---- issue next-chunk loads in the MMA shadow ----
        if (c + 1 < NCH) load_chunk(st ^ 1, c + 1);
        CP_COMMIT();

        // ---- ks = 1..5 ----
        #pragma unroll
        for (int ks = 1; ks < NKS; ks++) {
            uint32_t koff = (uint32_t)ks * 32;
            uint32_t bh[8];
            #pragma unroll
            for (int q = 0; q < 2; q++)
                ldmx4(&bh[q * 4], base + OFF_B + bw + (uint32_t)(q * 16) * ROWB + koff + b_off);
            #pragma unroll
            for (int mf = 0; mf < 4; mf++) {
                uint32_t ah[4];
                uint32_t arow = aw + (uint32_t)(mf * 16) * ROWB + koff;
                ldmx4(ah, base + OFF_A + arow + a_off);
                #pragma unroll
                for (int nf = 0; nf < 4; nf++)
                    mma16816(acc[mf][nf], ah, &bh[nf * 2]);
            }
        }
        st ^= 1;
    }

    // ---------------- epilogue ----------------
    const int rbase = m0 + wm * 64 + (lane >> 2);
    const int cbase = n0 + wn * 32 + 2 * (lane & 3);

    #pragma unroll
    for (int nf = 0; nf < 4; nf++) {
        int c0 = cbase + nf * 8;
        if (EPI == 1) {
            float2 bia = *(const float2*)&g_b1f[e * H_ + c0];
            #pragma unroll
            for (int mf = 0; mf < 4; mf++) {
                int r0 = rbase + mf * 16;
                #pragma unroll
                for (int half = 0; half < 2; half++) {
                    int r = r0 + half * 8;
                    float v0 = acc[mf][nf][half * 2 + 0] + bia.x;
                    float v1 = acc[mf][nf][half * 2 + 1] + bia.y;
                    v0 = 0.5f * v0 * (1.0f + erff(v0 * 0.70710678118654752f));
                    v1 = 0.5f * v1 * (1.0f + erff(v1 * 0.70710678118654752f));
                    __half2 hh;
                    hh.x = __float2half_rn(v0);
                    hh.y = __float2half_rn(v1);
                    *(__half2*)(g_h + ((size_t)e * B_ + r) * H_ + c0) = hh;
                }
            }
        } else {
            if (c0 < C_) {
                float2 bia = *(const float2*)&b2[e * C_ + c0];
                #pragma unroll
                for (int mf = 0; mf < 4; mf++) {
                    int r0 = rbase + mf * 16;
                    #pragma unroll
                    for (int half = 0; half < 2; half++) {
                        int r = r0 + half * 8;
                        float2 v;
                        v.x = acc[mf][nf][half * 2 + 0] + bia.x;
                        v.y = acc[mf][nf][half * 2 + 1] + bia.y;
                        *(float2*)(allp + ((size_t)e * B_ + r) * C_ + c0) = v;
                    }
                }
            }
        }
    }
}

// ===================================================================
// Fused softmax + mixture. One block per batch row b, 512 threads.
// 3-pass (max / exp-sum / normalize-write); 3 blocks/SM resident.
// ===================================================================
__global__ __launch_bounds__(512, 3) void softmax_mix_kernel(
    float* __restrict__ allp, float* __restrict__ market) {
    int b = blockIdx.x;
    int tid = threadIdx.x;
    int w = tid >> 5, lane = tid & 31;

    __shared__ float4 ssel[TK_][250];
    __shared__ float sw[TK_];
    __shared__ int sidx[TK_];
    if (tid < TK_) {
        sidx[tid] = g_tidx[b * TK_ + tid];
        sw[tid] = g_tw[b * TK_ + tid];
    }
    __syncthreads();

    int e = w;
    float4* row = (float4*)(allp + ((size_t)e * B_ + b) * C_);
    int sel = -1;
    #pragma unroll
    for (int k = 0; k < TK_; k++)
        if (sidx[k] == e) sel = k;

    // pass 1: max
    float m = -3.4e38f;
    #pragma unroll
    for (int i = 0; i < 8; i++) {
        int idx = i * 32 + lane;
        if (idx < 250) {
            float4 x = row[idx];
            m = fmaxf(m, fmaxf(fmaxf(x.x, x.y), fmaxf(x.z, x.w)));
        }
    }
    #pragma unroll
    for (int o = 16; o > 0; o >>= 1)
        m = fmaxf(m, __shfl_xor_sync(0xffffffffu, m, o));

    // pass 2: exp-sum
    float s = 0.f;
    #pragma unroll
    for (int i = 0; i < 8; i++) {
        int idx = i * 32 + lane;
        if (idx < 250) {
            float4 x = row[idx];
            x.x = expf(x.x - m); x.y = expf(x.y - m);
            x.z = expf(x.z - m); x.w = expf(x.w - m);
            s += x.x + x.y + x.z + x.w;
        }
    }
    #pragma unroll
    for (int o = 16; o > 0; o >>= 1)
        s += __shfl_xor_sync(0xffffffffu, s, o);
    float inv = 1.f / s;

    // pass 3: normalize + write (+stash selected rows)
    #pragma unroll
    for (int i = 0; i < 8; i++) {
        int idx = i * 32 + lane;
        if (idx < 250) {
            float4 x = row[idx];
            x.x = expf(x.x - m) * inv; x.y = expf(x.y - m) * inv;
            x.z = expf(x.z - m) * inv; x.w = expf(x.w - m) * inv;
            row[idx] = x;
            if (sel >= 0) ssel[sel][idx] = x;
        }
    }
    __syncthreads();

    if (tid < 250) {
        float w0 = sw[0], w1 = sw[1], w2 = sw[2], w3 = sw[3];
        float4 a0 = ssel[0][tid], a1 = ssel[1][tid], a2 = ssel[2][tid], a3 = ssel[3][tid];
        float4 r;
        r.x = w0 * a0.x + w1 * a1.x + w2 * a2.x + w3 * a3.x;
        r.y = w0 * a0.y + w1 * a1.y + w2 * a2.y + w3 * a3.y;
        r.z = w0 * a0.z + w1 * a1.z + w2 * a2.z + w3 * a3.z;
        r.w = w0 * a0.w + w1 * a1.w + w2 * a2.w + w3 * a3.w;
        ((float4*)(market + (size_t)b * C_))[tid] = r;
    }
}

// ===================================================================
extern "C" void kernel_launch(void* const* d_in, const int* in_sizes, int n_in,
                              void* d_out, int out_size) {
    (void)in_sizes; (void)n_in; (void)out_size;
    const float* features = (const float*)d_in[0];
    const float* router_w = (const float*)d_in[1];
    const float* router_b = (const float*)d_in[2];
    const float* ln_g     = (const float*)d_in[3];
    const float* ln_b     = (const float*)d_in[4];
    const float* w1       = (const float*)d_in[5];
    const float* b1       = (const float*)d_in[6];
    const float* w2       = (const float*)d_in[7];
    const float* b2       = (const float*)d_in[8];

    float* out    = (float*)d_out;
    float* market = out + MARKET_OFF;
    float* allp   = out + ALL_OFF;
    float* gate   = out + GATE_OFF;

    cudaFuncSetAttribute(gemm_mma_kernel<1>,
                         cudaFuncAttributeMaxDynamicSharedMemorySize, GEMM_SMEM);
    cudaFuncSetAttribute(gemm_mma_kernel<2>,
                         cudaFuncAttributeMaxDynamicSharedMemorySize, GEMM_SMEM);

    router_ln_kernel<<<B_, 256>>>(features, router_w, router_b, b1, gate);
    prep_w_kernel<<<dim3(32, 24, 32), dim3(32, 8)>>>(w1, ln_g, ln_b, w2);

    gemm_mma_kernel<1><<<dim3(H_ / 128, B_ / 128, E_), 256, GEMM_SMEM>>>(b2, allp);
    gemm_mma_kernel<2><<<dim3(1024 / 128, B_ / 128, E_), 256, GEMM_SMEM>>>(b2, allp);

    softmax_mix_kernel<<<B_, 512>>>(allp, market);
}

// round 17
// speedup vs baseline: 1.0606x; 1.0606x over previous
#include <cuda_runtime.h>
#include <cuda_fp16.h>
#include <math.h>
#include <stdint.h>

#define B_ 4096
#define D_ 768
#define E_ 16
#define H_ 768
#define C_ 1000
#define TK_ 4

#define MARKET_OFF 0
#define ALL_OFF    ((size_t)B_ * C_)
#define GATE_OFF   (ALL_OFF + (size_t)E_ * B_ * C_)

// ---------------- device scratch ----------------
__device__ __half g_xn[(size_t)B_ * D_];
__device__ __half g_w1t[(size_t)E_ * H_ * D_];     // [e][h][d], ln_g folded
__device__ __half g_w2t[(size_t)E_ * 1024 * H_];   // [e][c pad1024][h]
__device__ __half g_h[(size_t)E_ * B_ * H_];       // [e][b][h], gelu output
__device__ float g_b1f[E_ * H_];
__device__ int   g_tidx[B_ * TK_];
__device__ float g_tw[B_ * TK_];

// ---------------- PTX helpers (target-portable only) ----------------
__device__ __forceinline__ uint32_t smem_u32(const void* p) {
    uint32_t a;
    asm("{ .reg .u64 t; cvta.to.shared.u64 t, %1; cvt.u32.u64 %0, t; }"
        : "=r"(a) : "l"(p));
    return a;
}
__device__ __forceinline__ void cp16(uint32_t dst, const void* src) {
    asm volatile("cp.async.cg.shared.global [%0], [%1], 16;" :: "r"(dst), "l"(src));
}
#define CP_COMMIT() asm volatile("cp.async.commit_group;" ::: "memory")
#define CP_WAIT(n)  asm volatile("cp.async.wait_group %0;" :: "n"(n) : "memory")

__device__ __forceinline__ void ldmx4(uint32_t* r, uint32_t addr) {
    asm volatile("ldmatrix.sync.aligned.m8n8.x4.shared.b16 {%0,%1,%2,%3}, [%4];"
                 : "=r"(r[0]), "=r"(r[1]), "=r"(r[2]), "=r"(r[3]) : "r"(addr));
}
__device__ __forceinline__ void mma16816(float* d, const uint32_t* a, const uint32_t* b) {
    asm volatile(
        "mma.sync.aligned.m16n8k16.row.col.f32.f16.f16.f32 "
        "{%0,%1,%2,%3}, {%4,%5,%6,%7}, {%8,%9}, {%0,%1,%2,%3};"
        : "+f"(d[0]), "+f"(d[1]), "+f"(d[2]), "+f"(d[3])
        : "r"(a[0]), "r"(a[1]), "r"(a[2]), "r"(a[3]), "r"(b[0]), "r"(b[1]));
}

// ===================================================================
// Merged weight prep: z<16 -> w1 (transpose + ln_g fold + b1f atomics,
// 24x24 tile grid), z>=16 -> w2 (transpose + pad, 32x24 tile grid).
// ===================================================================
__global__ void prep_w_kernel(const float* __restrict__ w1,
                              const float* __restrict__ ln_g,
                              const float* __restrict__ ln_b,
                              const float* __restrict__ w2) {
    __shared__ float t[32][33];
    int tx = threadIdx.x, ty = threadIdx.y;
    int z = blockIdx.z;

    if (z < E_) {
        // w1 grid: x in [0,24) h-blocks, y in [0,24) d-blocks
        if (blockIdx.x >= 24) return;
        __shared__ float ps[8][32];
        int e = z;
        int h0 = blockIdx.x * 32, d0 = blockIdx.y * 32;
        float part = 0.f;
        #pragma unroll
        for (int i = 0; i < 32; i += 8) {
            int d = d0 + ty + i;
            float raw = w1[((size_t)e * D_ + d) * H_ + h0 + tx];
            part += ln_b[e * D_ + d] * raw;
            t[ty + i][tx] = ln_g[e * D_ + d] * raw;
        }
        ps[ty][tx] = part;
        __syncthreads();
        if (ty == 0) {
            float acc = 0.f;
            #pragma unroll
            for (int q = 0; q < 8; q++) acc += ps[q][tx];
            atomicAdd(&g_b1f[e * H_ + h0 + tx], acc);
        }
        #pragma unroll
        for (int i = 0; i < 32; i += 8) {
            int h = h0 + ty + i;
            g_w1t[((size_t)e * H_ + h) * D_ + d0 + tx] =
                __float2half_rn(t[tx][ty + i]);
        }
    } else {
        int e = z - E_;
        int c0 = blockIdx.x * 32, h0 = blockIdx.y * 32;
        #pragma unroll
        for (int i = 0; i < 32; i += 8) {
            int h = h0 + ty + i;
            int c = c0 + tx;
            t[ty + i][tx] = (c < C_) ? w2[((size_t)e * H_ + h) * C_ + c] : 0.f;
        }
        __syncthreads();
        #pragma unroll
        for (int i = 0; i < 32; i += 8) {
            int c = c0 + ty + i;
            g_w2t[((size_t)e * 1024 + c) * H_ + h0 + tx] =
                __float2half_rn(t[tx][ty + i]);
        }
    }
}

// ===================================================================
// Router + LayerNorm (writes xn as fp16). First 48 blocks also seed
// g_b1f = b1 (router runs before prep_w, so ordering is safe).
// ===================================================================
__global__ __launch_bounds__(256) void router_ln_kernel(
    const float* __restrict__ F, const float* __restrict__ RW,
    const float* __restrict__ RB, const float* __restrict__ b1,
    float* __restrict__ gate_out) {
    int b = blockIdx.x;
    int tid = threadIdx.x;

    if (b < 48) {
        int i = b * 256 + tid;
        if (i < E_ * H_) g_b1f[i] = b1[i];
    }

    __shared__ float xs[D_];
    __shared__ float red[256];
    __shared__ float red2[256];
    __shared__ float gl[16][17];
    __shared__ float smean, srstd;

    const float* f = F + (size_t)b * D_;
    float s = 0.f, s2 = 0.f;
    for (int i = tid; i < D_; i += 256) {
        float v = f[i];
        xs[i] = v; s += v; s2 += v * v;
    }
    red[tid] = s; red2[tid] = s2;
    __syncthreads();
    for (int o = 128; o > 0; o >>= 1) {
        if (tid < o) { red[tid] += red[tid + o]; red2[tid] += red2[tid + o]; }
        __syncthreads();
    }
    if (tid == 0) {
        float mean = red[0] * (1.f / D_);
        float var = red2[0] * (1.f / D_) - mean * mean;
        smean = mean;
        srstd = rsqrtf(var + 1e-5f);
    }
    __syncthreads();
    float mean = smean, rstd = srstd;
    for (int i = tid; i < D_; i += 256)
        g_xn[(size_t)b * D_ + i] = __float2half_rn((xs[i] - mean) * rstd);

    int e = tid & 15, p = tid >> 4;
    float acc = 0.f;
    for (int d = p; d < D_; d += 16) acc += xs[d] * RW[d * E_ + e];
    gl[p][e] = acc;
    __syncthreads();
    if (tid < 16) {
        float l = RB[tid];
        #pragma unroll
        for (int q = 0; q < 16; q++) l += gl[q][tid];
        red[tid] = l;
    }
    __syncthreads();
    if (tid == 0) {
        float lg[16];
        float mx = -3.4e38f;
        #pragma unroll
        for (int i = 0; i < 16; i++) { lg[i] = red[i]; mx = fmaxf(mx, lg[i]); }
        float sum = 0.f;
        #pragma unroll
        for (int i = 0; i < 16; i++) { lg[i] = expf(lg[i] - mx); sum += lg[i]; }
        float inv = 1.f / sum;
        #pragma unroll
        for (int i = 0; i < 16; i++) {
            lg[i] *= inv;
            gate_out[(size_t)b * 16 + i] = lg[i];
        }
        float tmp[16];
        #pragma unroll
        for (int i = 0; i < 16; i++) tmp[i] = lg[i];
        int idx[TK_]; float val[TK_]; float vs = 0.f;
        for (int k = 0; k < TK_; k++) {
            int bj = 0; float bv = tmp[0];
            #pragma unroll
            for (int j = 1; j < 16; j++)
                if (tmp[j] > bv) { bv = tmp[j]; bj = j; }
            idx[k] = bj; val[k] = bv; vs += bv;
            tmp[bj] = -1.f;
        }
        float ivs = 1.f / vs;
        for (int k = 0; k < TK_; k++) {
            g_tidx[b * TK_ + k] = idx[k];
            g_tw[b * TK_ + k] = val[k] * ivs;
        }
    }
}

// ===================================================================
// mma.sync GEMM (R14 config, best measured): CTA 128x128x64, 8 warps
// (2m x 4n), warp tile 64x32, STAGES=3, 2 CTAs/SM. Next-chunk cp.async
// issued in the ks=0 MMA shadow. single-pass fp16, fp32 accum. K=768.
// EPI=1: A=xn, B=w1t; epilogue bias+gelu -> g_h (fp16)
// EPI=2: A=g_h, B=w2t; epilogue bias -> allp fp32 (bounds C=1000)
// ===================================================================
#define BK 64
#define STAGES 3
#define ROWB 144u                 // 64 fp16 + 16B pad (conflict-free ldmatrix)
#define OFF_A 0u
#define OFF_B 18432u              // 128*144
#define STG   36864u              // 256*144
#define GEMM_SMEM (STAGES * 36864)  // 110592
#define NCH (D_ / BK)             // 12

template <int EPI>
__global__ __launch_bounds__(256, 2) void gemm_mma_kernel(
    const float* __restrict__ b2, float* __restrict__ allp) {
    const int e  = blockIdx.z;
    const int m0 = blockIdx.y * 128;
    const int n0 = blockIdx.x * 128;
    const int tid  = threadIdx.x;
    const int lane = tid & 31;
    const int wid  = tid >> 5;
    const int wm   = wid >> 2;   // 0..1
    const int wn   = wid & 3;    // 0..3

    extern __shared__ char smem[];
    uint32_t sb = smem_u32(smem);

    const char *gA, *gB;
    if (EPI == 1) {
        gA = (const char*)(g_xn + (size_t)m0 * D_);
        gB = (const char*)(g_w1t + ((size_t)e * H_ + n0) * D_);
    } else {
        gA = (const char*)(g_h + ((size_t)e * B_ + m0) * H_);
        gB = (const char*)(g_w2t + ((size_t)e * 1024 + n0) * H_);
    }

    auto load_chunk = [&](int stage, int kc) {
        uint32_t base = sb + (uint32_t)stage * STG;
        size_t kb = (size_t)kc * 128;            // 64 fp16 = 128 B along K
        #pragma unroll
        for (int it = 0; it < 4; it++) {          // A: 128 rows x 8 segs
            int id = tid + it * 256;
            int r = id >> 3, ch = id & 7;
            uint32_t so = (uint32_t)r * ROWB + ch * 16;
            size_t go = (size_t)r * 1536 + kb + ch * 16;
            cp16(base + OFF_A + so, gA + go);
        }
        #pragma unroll
        for (int it = 0; it < 4; it++) {          // B: 128 rows x 8 segs
            int id = tid + it * 256;
            int r = id >> 3, ch = id & 7;
            uint32_t so = (uint32_t)r * ROWB + ch * 16;
            size_t go = (size_t)r * 1536 + kb + ch * 16;
            cp16(base + OFF_B + so, gB + go);
        }
    };

    float acc[4][4][4];
    #pragma unroll
    for (int i = 0; i < 4; i++)
        #pragma unroll
        for (int j = 0; j < 4; j++)
            #pragma unroll
            for (int q = 0; q < 4; q++) acc[i][j][q] = 0.f;

    const uint32_t a_off = (uint32_t)(lane & 15) * ROWB + (uint32_t)(lane >> 4) * 16;
    const uint32_t b_off = ((uint32_t)((lane & 7) + ((lane >> 4) << 3))) * ROWB +
                           (uint32_t)((lane >> 3) & 1) * 16;
    const uint32_t aw = (uint32_t)(wm * 64) * ROWB;
    const uint32_t bw = (uint32_t)(wn * 32) * ROWB;

    // prologue: fill STAGES-1 buffers
    #pragma unroll
    for (int s = 0; s < STAGES - 1; s++) {
        load_chunk(s, s);
        CP_COMMIT();
    }

    int st = 0;
    for (int c = 0; c < NCH; c++) {
        CP_WAIT(STAGES - 2);
        __syncthreads();

        uint32_t base = sb + (uint32_t)st * STG;

        // ---- ks = 0: straight to ldsm+MMA after the barrier ----
        {
            uint32_t bh[8];
            #pragma unroll
            for (int q = 0; q < 2; q++)
                ldmx4(&bh[q * 4], base + OFF_B + bw + (uint32_t)(q * 16) * ROWB + b_off);
            #pragma unroll
            for (int mf = 0; mf < 4; mf++) {
                uint32_t ah[4];
                ldmx4(ah, base + OFF_A + aw + (uint32_t)(mf * 16) * ROWB + a_off);
                #pragma unroll
                for (int nf = 0; nf < 4; nf++)
                    mma16816(acc[mf][nf], ah, &bh[nf * 2]);
            }
        }

        // ---- issue next-chunk loads in the MMA shadow ----
        if (c + STAGES - 1 < NCH) {
            int ls = st + (STAGES - 1);
            if (ls >= STAGES) ls -= STAGES;
            load_chunk(ls, c + STAGES - 1);
        }
        CP_COMMIT();

        // ---- ks = 1..3 ----
        #pragma unroll
        for (int ks = 1; ks < 4; ks++) {
            uint32_t koff = (uint32_t)ks * 32;
            uint32_t bh[8];
            #pragma unroll
            for (int q = 0; q < 2; q++)
                ldmx4(&bh[q * 4], base + OFF_B + bw + (uint32_t)(q * 16) * ROWB + koff + b_off);
            #pragma unroll
            for (int mf = 0; mf < 4; mf++) {
                uint32_t ah[4];
                uint32_t arow = aw + (uint32_t)(mf * 16) * ROWB + koff;
                ldmx4(ah, base + OFF_A + arow + a_off);
                #pragma unroll
                for (int nf = 0; nf < 4; nf++)
                    mma16816(acc[mf][nf], ah, &bh[nf * 2]);
            }
        }
        st++;
        if (st == STAGES) st = 0;
    }

    // ---------------- epilogue ----------------
    const int rbase = m0 + wm * 64 + (lane >> 2);
    const int cbase = n0 + wn * 32 + 2 * (lane & 3);

    #pragma unroll
    for (int nf = 0; nf < 4; nf++) {
        int c0 = cbase + nf * 8;
        if (EPI == 1) {
            float2 bia = *(const float2*)&g_b1f[e * H_ + c0];
            #pragma unroll
            for (int mf = 0; mf < 4; mf++) {
                int r0 = rbase + mf * 16;
                #pragma unroll
                for (int half = 0; half < 2; half++) {
                    int r = r0 + half * 8;
                    float v0 = acc[mf][nf][half * 2 + 0] + bia.x;
                    float v1 = acc[mf][nf][half * 2 + 1] + bia.y;
                    v0 = 0.5f * v0 * (1.0f + erff(v0 * 0.70710678118654752f));
                    v1 = 0.5f * v1 * (1.0f + erff(v1 * 0.70710678118654752f));
                    __half2 hh;
                    hh.x = __float2half_rn(v0);
                    hh.y = __float2half_rn(v1);
                    *(__half2*)(g_h + ((size_t)e * B_ + r) * H_ + c0) = hh;
                }
            }
        } else {
            if (c0 < C_) {
                float2 bia = *(const float2*)&b2[e * C_ + c0];
                #pragma unroll
                for (int mf = 0; mf < 4; mf++) {
                    int r0 = rbase + mf * 16;
                    #pragma unroll
                    for (int half = 0; half < 2; half++) {
                        int r = r0 + half * 8;
                        float2 v;
                        v.x = acc[mf][nf][half * 2 + 0] + bia.x;
                        v.y = acc[mf][nf][half * 2 + 1] + bia.y;
                        *(float2*)(allp + ((size_t)e * B_ + r) * C_ + c0) = v;
                    }
                }
            }
        }
    }
}

// ===================================================================
// Fused softmax + mixture. One block per batch row b, 512 threads.
// 3-pass (max / exp-sum / normalize-write); 3 blocks/SM resident.
// ===================================================================
__global__ __launch_bounds__(512, 3) void softmax_mix_kernel(
    float* __restrict__ allp, float* __restrict__ market) {
    int b = blockIdx.x;
    int tid = threadIdx.x;
    int w = tid >> 5, lane = tid & 31;

    __shared__ float4 ssel[TK_][250];
    __shared__ float sw[TK_];
    __shared__ int sidx[TK_];
    if (tid < TK_) {
        sidx[tid] = g_tidx[b * TK_ + tid];
        sw[tid] = g_tw[b * TK_ + tid];
    }
    __syncthreads();

    int e = w;
    float4* row = (float4*)(allp + ((size_t)e * B_ + b) * C_);
    int sel = -1;
    #pragma unroll
    for (int k = 0; k < TK_; k++)
        if (sidx[k] == e) sel = k;

    // pass 1: max
    float m = -3.4e38f;
    #pragma unroll
    for (int i = 0; i < 8; i++) {
        int idx = i * 32 + lane;
        if (idx < 250) {
            float4 x = row[idx];
            m = fmaxf(m, fmaxf(fmaxf(x.x, x.y), fmaxf(x.z, x.w)));
        }
    }
    #pragma unroll
    for (int o = 16; o > 0; o >>= 1)
        m = fmaxf(m, __shfl_xor_sync(0xffffffffu, m, o));

    // pass 2: exp-sum
    float s = 0.f;
    #pragma unroll
    for (int i = 0; i < 8; i++) {
        int idx = i * 32 + lane;
        if (idx < 250) {
            float4 x = row[idx];
            x.x = expf(x.x - m); x.y = expf(x.y - m);
            x.z = expf(x.z - m); x.w = expf(x.w - m);
            s += x.x + x.y + x.z + x.w;
        }
    }
    #pragma unroll
    for (int o = 16; o > 0; o >>= 1)
        s += __shfl_xor_sync(0xffffffffu, s, o);
    float inv = 1.f / s;

    // pass 3: normalize + write (+stash selected rows)
    #pragma unroll
    for (int i = 0; i < 8; i++) {
        int idx = i * 32 + lane;
        if (idx < 250) {
            float4 x = row[idx];
            x.x = expf(x.x - m) * inv; x.y = expf(x.y - m) * inv;
            x.z = expf(x.z - m) * inv; x.w = expf(x.w - m) * inv;
            row[idx] = x;
            if (sel >= 0) ssel[sel][idx] = x;
        }
    }
    __syncthreads();

    if (tid < 250) {
        float w0 = sw[0], w1 = sw[1], w2 = sw[2], w3 = sw[3];
        float4 a0 = ssel[0][tid], a1 = ssel[1][tid], a2 = ssel[2][tid], a3 = ssel[3][tid];
        float4 r;
        r.x = w0 * a0.x + w1 * a1.x + w2 * a2.x + w3 * a3.x;
        r.y = w0 * a0.y + w1 * a1.y + w2 * a2.y + w3 * a3.y;
        r.z = w0 * a0.z + w1 * a1.z + w2 * a2.z + w3 * a3.z;
        r.w = w0 * a0.w + w1 * a1.w + w2 * a2.w + w3 * a3.w;
        ((float4*)(market + (size_t)b * C_))[tid] = r;
    }
}

// ===================================================================
extern "C" void kernel_launch(void* const* d_in, const int* in_sizes, int n_in,
                              void* d_out, int out_size) {
    (void)in_sizes; (void)n_in; (void)out_size;
    const float* features = (const float*)d_in[0];
    const float* router_w = (const float*)d_in[1];
    const float* router_b = (const float*)d_in[2];
    const float* ln_g     = (const float*)d_in[3];
    const float* ln_b     = (const float*)d_in[4];
    const float* w1       = (const float*)d_in[5];
    const float* b1       = (const float*)d_in[6];
    const float* w2       = (const float*)d_in[7];
    const float* b2       = (const float*)d_in[8];

    float* out    = (float*)d_out;
    float* market = out + MARKET_OFF;
    float* allp   = out + ALL_OFF;
    float* gate   = out + GATE_OFF;

    cudaFuncSetAttribute(gemm_mma_kernel<1>,
                         cudaFuncAttributeMaxDynamicSharedMemorySize, GEMM_SMEM);
    cudaFuncSetAttribute(gemm_mma_kernel<2>,
                         cudaFuncAttributeMaxDynamicSharedMemorySize, GEMM_SMEM);

    router_ln_kernel<<<B_, 256>>>(features, router_w, router_b, b1, gate);
    prep_w_kernel<<<dim3(32, 24, 32), dim3(32, 8)>>>(w1, ln_g, ln_b, w2);

    gemm_mma_kernel<1><<<dim3(H_ / 128, B_ / 128, E_), 256, GEMM_SMEM>>>(b2, allp);
    gemm_mma_kernel<2><<<dim3(1024 / 128, B_ / 128, E_), 256, GEMM_SMEM>>>(b2, allp);

    softmax_mix_kernel<<<B_, 512>>>(allp, market);
}